// round 10
// baseline (speedup 1.0000x reference)
#include <cuda_runtime.h>
#include <cuda_bf16.h>
#include <cstdint>

#define NB    16
#define NPTS  4096
#define SPTS  1024
#define COLS  65536
#define JCOLS 16384

// fp32 scratch
__device__ __align__(16) float g_Z[3u * 16384u * 256u];   // Z[k][col][o] o-contig
__device__ __align__(16) float g_Y[256u * 65536u];
__device__ __align__(16) float g_O2[128u * 65536u];
__device__ int   g_idx[65536 * 3];
__device__ float g_w[65536 * 3];
__device__ float g_sum0[256], g_sq0[256], g_a0[256], g_c0[256];
__device__ float g_sum1[128], g_sq1[128], g_a1[128], g_c1[128];

__device__ __forceinline__ void mma16816(float* d, const uint32_t* a, const uint32_t* b) {
    asm volatile("mma.sync.aligned.m16n8k16.row.col.f32.bf16.bf16.f32 "
                 "{%0,%1,%2,%3}, {%4,%5,%6,%7}, {%8,%9}, {%0,%1,%2,%3};"
                 : "+f"(d[0]), "+f"(d[1]), "+f"(d[2]), "+f"(d[3])
                 : "r"(a[0]), "r"(a[1]), "r"(a[2]), "r"(a[3]), "r"(b[0]), "r"(b[1]));
}
__device__ __forceinline__ uint32_t bf2u(__nv_bfloat16 a, __nv_bfloat16 b) {
    return (uint32_t)__bfloat16_as_ushort(a) | ((uint32_t)__bfloat16_as_ushort(b) << 16);
}
__device__ __forceinline__ void split2(float v0, float v1, uint32_t& hi, uint32_t& lo) {
    const __nv_bfloat16 h0 = __float2bfloat16(v0), h1 = __float2bfloat16(v1);
    hi = bf2u(h0, h1);
    lo = bf2u(__float2bfloat16(v0 - __bfloat162float(h0)),
              __float2bfloat16(v1 - __bfloat162float(h1)));
}

// smem fragment-permuted layout. Atom = 512B payload, 544B stride (bank spread).
// A tile 128m x 32k: atoms (ka<2, ma<8), idx = ka*8+ma. value A[m][k]:
//   lane = (m&7)*4 + ((k&7)>>1), reg = ((k&15)>=8)*2 + ((m&15)>=8), pos = k&1
// B tile 32k x 128n: atoms (ka<2, na2<8), idx = ka*8+na2. value B[k][n]:
//   lane = (n&7)*4 + ((k&7)>>1), reg = ((n&15)>=8)*2 + ((k&15)>=8), pos = k&1
#define A_HI  0
#define A_LO  8704
#define B_HI  17408
#define B_LO  26112
#define STAGE_SZ 34816
#define SMEM_BYTES 69632

// ======== core mainloop: D[128x128] += A[128xK] * B[KxN..]^T, 3-term bf16 split ======
// aSrc fp32 [m][k] pitch aPitch; bSrc fp32 [k][n] pitch B_LD. NT = K/32 tiles.
// acc[am 2][bn 4][4] per warp (16 warps: wm=w>>2 m32, wn=w&3 n32).
template<int NT, bool BN>
__device__ __forceinline__ void mma_tile(char* sm,
        const float* aSrc, int aPitch, const float* bSrc, int B_LD,
        const float* bnA, const float* bnC, float acc[2][4][4]) {
    const int t = threadIdx.x;
    const int L = t & 31, w = t >> 5;
    const int wm = w >> 2, wn = w & 3;
    // loader indices
    const int lm = t >> 2;              // A: m row 0..127
    const int lkq = (t & 3) * 8;        // A: k base, covers lkq..lkq+7
    const int lbn = (t & 31) * 4;       // B: n base
    const int lbk = (t >> 5) * 2;       // B: k rows lbk, lbk+1

    float4 aP0, aP1, bP0, bP1;

    auto ldg = [&](int kt) {
        const float* a = aSrc + (size_t)lm * aPitch + kt * 32 + lkq;
        aP0 = *(const float4*)a;
        aP1 = *(const float4*)(a + 4);
        const float* b = bSrc + (size_t)(kt * 32 + lbk) * B_LD + lbn;
        bP0 = *(const float4*)b;
        bP1 = *(const float4*)(b + B_LD);
    };

    auto stsA4 = [&](int soff, int kq, float4 v) {
        uint32_t hi0, lo0, hi1, lo1;
        split2(v.x, v.y, hi0, lo0);
        split2(v.z, v.w, hi1, lo1);
        const int tig = (kq & 7) >> 1;
        const int r = (((kq & 15) >= 8) ? 2 : 0) + (((lm & 15) >= 8) ? 1 : 0);
        const int atom = (kq >> 4) * 8 + (lm >> 4);
        const int base = soff + atom * 544 + ((lm & 7) * 4 + tig) * 16 + r * 4;
        *(uint32_t*)(sm + A_HI + base)      = hi0;
        *(uint32_t*)(sm + A_HI + base + 16) = hi1;
        *(uint32_t*)(sm + A_LO + base)      = lo0;
        *(uint32_t*)(sm + A_LO + base + 16) = lo1;
    };

    auto sts = [&](int kt) {
        const int soff = (kt & 1) * STAGE_SZ;
        stsA4(soff, lkq, aP0);
        stsA4(soff, lkq + 4, aP1);
        float4 v0 = bP0, v1 = bP1;
        if (BN) {
            const int kabs = kt * 32 + lbk;
            const float a0v = bnA[kabs], c0v = bnC[kabs];
            const float a1v = bnA[kabs + 1], c1v = bnC[kabs + 1];
            v0.x = fmaxf(0.f, fmaf(a0v, v0.x, c0v));
            v0.y = fmaxf(0.f, fmaf(a0v, v0.y, c0v));
            v0.z = fmaxf(0.f, fmaf(a0v, v0.z, c0v));
            v0.w = fmaxf(0.f, fmaf(a0v, v0.w, c0v));
            v1.x = fmaxf(0.f, fmaf(a1v, v1.x, c1v));
            v1.y = fmaxf(0.f, fmaf(a1v, v1.y, c1v));
            v1.z = fmaxf(0.f, fmaf(a1v, v1.z, c1v));
            v1.w = fmaxf(0.f, fmaf(a1v, v1.w, c1v));
        }
        const float e0[4] = {v0.x, v0.y, v0.z, v0.w};
        const float e1[4] = {v1.x, v1.y, v1.z, v1.w};
        const int tig = (lbk & 7) >> 1;
        const int kb = ((lbk & 15) >= 8) ? 1 : 0;
        const int ka = lbk >> 4;
#pragma unroll
        for (int j = 0; j < 4; j++) {
            const int n = lbn + j;
            uint32_t hi, lo;
            split2(e0[j], e1[j], hi, lo);
            const int r = (((n & 15) >= 8) ? 2 : 0) + kb;
            const int base = soff + (ka * 8 + (n >> 4)) * 544 + ((n & 7) * 4 + tig) * 16 + r * 4;
            *(uint32_t*)(sm + B_HI + base) = hi;
            *(uint32_t*)(sm + B_LO + base) = lo;
        }
    };

#pragma unroll
    for (int am = 0; am < 2; am++)
#pragma unroll
        for (int bn = 0; bn < 4; bn++)
#pragma unroll
            for (int d = 0; d < 4; d++) acc[am][bn][d] = 0.f;

    ldg(0); sts(0); ldg(1);

#pragma unroll 1
    for (int kt = 0; kt < NT; kt++) {
        __syncthreads();
        if (kt + 1 < NT) sts(kt + 1);
        if (kt + 2 < NT) ldg(kt + 2);
        const int soff = (kt & 1) * STAGE_SZ;
#pragma unroll
        for (int ks = 0; ks < 2; ks++) {
            uint32_t ah[2][4], al[2][4], bh[2][4], bl[2][4];
#pragma unroll
            for (int am = 0; am < 2; am++) {
                const int off = soff + (ks * 8 + wm * 2 + am) * 544 + L * 16;
                *(uint4*)ah[am] = *(const uint4*)(sm + A_HI + off);
                *(uint4*)al[am] = *(const uint4*)(sm + A_LO + off);
            }
#pragma unroll
            for (int b2 = 0; b2 < 2; b2++) {
                const int off = soff + (ks * 8 + wn * 2 + b2) * 544 + L * 16;
                *(uint4*)bh[b2] = *(const uint4*)(sm + B_HI + off);
                *(uint4*)bl[b2] = *(const uint4*)(sm + B_LO + off);
            }
#pragma unroll
            for (int am = 0; am < 2; am++)
#pragma unroll
                for (int bn = 0; bn < 4; bn++) {
                    const uint32_t* bhp = &bh[bn >> 1][(bn & 1) * 2];
                    const uint32_t* blp = &bl[bn >> 1][(bn & 1) * 2];
                    mma16816(acc[am][bn], ah[am], bhp);
                    mma16816(acc[am][bn], ah[am], blp);
                    mma16816(acc[am][bn], al[am], bhp);
                }
        }
    }
}

// ---------------- prep: zero stats ----------------
__global__ void prep_kernel() {
    const int t = threadIdx.x;
    if (t < 256) { g_sum0[t] = 0.f; g_sq0[t] = 0.f; }
    if (t < 128) { g_sum1[t] = 0.f; g_sq1[t] = 0.f; }
}

// ---------------- 3-NN search + interpolation weights ----------------
__global__ void knn_kernel(const float* __restrict__ xyz1,
                           const float* __restrict__ xyz2) {
    __shared__ float sx[SPTS], sy[SPTS], sz[SPTS], sn[SPTS];
    const int t = threadIdx.x;
    const int b = blockIdx.x >> 4;
    const int qbase = (blockIdx.x & 15) << 8;
    const float* base2 = xyz2 + (size_t)b * 3 * SPTS;
    for (int i = t; i < SPTS; i += 256) {
        float x = base2[i], y = base2[SPTS + i], z = base2[2 * SPTS + i];
        sx[i] = x; sy[i] = y; sz[i] = z; sn[i] = x * x + y * y + z * z;
    }
    __syncthreads();
    const int n = qbase + t;
    const float* base1 = xyz1 + (size_t)b * 3 * NPTS;
    const float qx = base1[n], qy = base1[NPTS + n], qz = base1[2 * NPTS + n];
    const float qn = qx * qx + qy * qy + qz * qz;
    float d0 = 3.4e38f, d1 = 3.4e38f, d2 = 3.4e38f;
    int i0 = 0, i1 = 0, i2 = 0;
#pragma unroll 4
    for (int s = 0; s < SPTS; s++) {
        float d = qn + sn[s] - 2.f * (qx * sx[s] + qy * sy[s] + qz * sz[s]);
        if (d < d2) {
            if (d < d1) {
                if (d < d0) { d2 = d1; i2 = i1; d1 = d0; i1 = i0; d0 = d; i0 = s; }
                else        { d2 = d1; i2 = i1; d1 = d;  i1 = s; }
            } else          { d2 = d;  i2 = s; }
        }
    }
    const float r0 = 1.f / (d0 + 1e-8f);
    const float r1 = 1.f / (d1 + 1e-8f);
    const float r2 = 1.f / (d2 + 1e-8f);
    const float inv = 1.f / (r0 + r1 + r2);
    const int col = b * NPTS + n;
    g_idx[col * 3 + 0] = i0; g_idx[col * 3 + 1] = i1; g_idx[col * 3 + 2] = i2;
    g_w[col * 3 + 0] = r0 * inv; g_w[col * 3 + 1] = r1 * inv; g_w[col * 3 + 2] = r2 * inv;
}

// frag scatter to smem C tile [128][132] fp32
#define FRAGS_TO_CS() \
    __syncthreads(); \
    float* Cs = (float*)sm; \
    { \
        const int L = threadIdx.x & 31, w = threadIdx.x >> 5; \
        const int wm = w >> 2, wn = w & 3; \
        _Pragma("unroll") \
        for (int am = 0; am < 2; am++) \
            _Pragma("unroll") \
            for (int an = 0; an < 4; an++) { \
                const int m = wm * 32 + am * 16 + (L >> 2); \
                const int n = wn * 32 + an * 8 + ((L & 3) << 1); \
                Cs[m * 132 + n]           = acc[am][an][0]; \
                Cs[m * 132 + n + 1]       = acc[am][an][1]; \
                Cs[(m + 8) * 132 + n]     = acc[am][an][2]; \
                Cs[(m + 8) * 132 + n + 1] = acc[am][an][3]; \
            } \
    } \
    __syncthreads();

// ---------------- GEMM Z: D[o 128][col 128], K=128 ----------------
__global__ __launch_bounds__(512) void gemmZ_mma(const float* __restrict__ w0,
                                                 const float* __restrict__ p2) {
    extern __shared__ __align__(16) char sm[];
    const int col0 = blockIdx.x * 128;
    const int kg = blockIdx.y >> 1;
    const int o0 = (blockIdx.y & 1) * 128;
    const int bb = col0 >> 10, sOff = col0 & 1023;

    float acc[2][4][4];
    mma_tile<4, false>(sm, w0 + (size_t)o0 * 512 + 128 + kg * 128, 512,
                       p2 + (size_t)bb * 131072 + sOff, 1024, nullptr, nullptr, acc);

    const int L = threadIdx.x & 31, w = threadIdx.x >> 5;
    const int wm = w >> 2, wn = w & 3;
#pragma unroll
    for (int am = 0; am < 2; am++)
#pragma unroll
        for (int an = 0; an < 4; an++) {
            const int m = o0 + wm * 32 + am * 16 + (L >> 2);
            const int n = col0 + wn * 32 + an * 8 + ((L & 3) << 1);
            float* z0 = g_Z + ((size_t)(kg * JCOLS + n)) * 256 + m;
            float* z1 = z0 + 256;
            z0[0] = acc[am][an][0];
            z1[0] = acc[am][an][1];
            z0[8] = acc[am][an][2];
            z1[8] = acc[am][an][3];
        }
}

// ---------------- GEMM Y: M=256 (2 y-blocks), K=128; gather+bias+stats ---------------
__global__ __launch_bounds__(512) void gemmY_mma(const float* __restrict__ w0,
                                                 const float* __restrict__ p1,
                                                 const float* __restrict__ bias0) {
    extern __shared__ __align__(16) char sm[];
    const int col0 = blockIdx.x * 128;
    const int m0 = blockIdx.y * 128;
    const int bb = col0 >> 12, nOff = col0 & 4095;

    float acc[2][4][4];
    mma_tile<4, false>(sm, w0 + (size_t)m0 * 512, 512,
                       p1 + (size_t)bb * 524288 + nOff, 4096, nullptr, nullptr, acc);

    FRAGS_TO_CS();

    const int t = threadIdx.x;
    const int tx = t & 15, ty = t >> 4;
    const int rowb = m0 + ty * 4;
    float a4[4][8];
#pragma unroll
    for (int i = 0; i < 4; i++) {
        float4 u0 = *(const float4*)&Cs[(ty * 4 + i) * 132 + tx * 8];
        float4 u1 = *(const float4*)&Cs[(ty * 4 + i) * 132 + tx * 8 + 4];
        a4[i][0] = u0.x; a4[i][1] = u0.y; a4[i][2] = u0.z; a4[i][3] = u0.w;
        a4[i][4] = u1.x; a4[i][5] = u1.y; a4[i][6] = u1.z; a4[i][7] = u1.w;
    }
    float bias[4];
#pragma unroll
    for (int i = 0; i < 4; i++) bias[i] = bias0[rowb + i];

#pragma unroll
    for (int j = 0; j < 8; j++) {
        const int col = col0 + tx * 8 + j;
        const int ia = g_idx[col * 3], ib = g_idx[col * 3 + 1], ic = g_idx[col * 3 + 2];
        const float wa = g_w[col * 3], wb = g_w[col * 3 + 1], wc = g_w[col * 3 + 2];
        const int jb = (col >> 12) << 10;
        float4 p0 = *(const float4*)(g_Z + ((size_t)(jb + ia)) * 256 + rowb);
        float4 q0 = *(const float4*)(g_Z + ((size_t)(JCOLS + jb + ib)) * 256 + rowb);
        float4 r0 = *(const float4*)(g_Z + ((size_t)(2 * JCOLS + jb + ic)) * 256 + rowb);
        a4[0][j] += bias[0] + wa * p0.x + wb * q0.x + wc * r0.x;
        a4[1][j] += bias[1] + wa * p0.y + wb * q0.y + wc * r0.y;
        a4[2][j] += bias[2] + wa * p0.z + wb * q0.z + wc * r0.z;
        a4[3][j] += bias[3] + wa * p0.w + wb * q0.w + wc * r0.w;
    }

    const int colT = col0 + tx * 8;
#pragma unroll
    for (int i = 0; i < 4; i++) {
        const int row = rowb + i;
        float* yp = g_Y + (size_t)row * COLS + colT;
        *(float4*)yp       = make_float4(a4[i][0], a4[i][1], a4[i][2], a4[i][3]);
        *(float4*)(yp + 4) = make_float4(a4[i][4], a4[i][5], a4[i][6], a4[i][7]);
        float s = 0.f, q = 0.f;
#pragma unroll
        for (int j = 0; j < 8; j++) { s += a4[i][j]; q += a4[i][j] * a4[i][j]; }
#pragma unroll
        for (int off = 8; off; off >>= 1) {
            s += __shfl_xor_sync(0xffffffffu, s, off);
            q += __shfl_xor_sync(0xffffffffu, q, off);
        }
        if ((t & 15) == 0) { atomicAdd(&g_sum0[row], s); atomicAdd(&g_sq0[row], q); }
    }
}

__global__ void finalize0(const float* __restrict__ gamma, const float* __restrict__ beta) {
    const int t = threadIdx.x;
    const float mean = g_sum0[t] * (1.f / COLS);
    const float var = g_sq0[t] * (1.f / COLS) - mean * mean;
    const float a = gamma[t] * rsqrtf(var + 1e-5f);
    g_a0[t] = a;
    g_c0[t] = beta[t] - mean * a;
}

// ---------------- GEMM O2: M=128, K=256; BN0+ReLU fused on B; stats ------------------
__global__ __launch_bounds__(512) void gemmO2_mma(const float* __restrict__ w1,
                                                  const float* __restrict__ bias1) {
    extern __shared__ __align__(16) char sm[];
    const int col0 = blockIdx.x * 128;

    float acc[2][4][4];
    mma_tile<8, true>(sm, w1, 256, g_Y + col0, 65536, g_a0, g_c0, acc);

    FRAGS_TO_CS();

    const int t = threadIdx.x;
    const int tx = t & 15, ty = t >> 4;
    const int rowb = ty * 4;
    const int colT = col0 + tx * 8;
#pragma unroll
    for (int i = 0; i < 4; i++) {
        const int row = rowb + i;
        const float bias = bias1[row];
        float a8[8];
        float4 u0 = *(const float4*)&Cs[row * 132 + tx * 8];
        float4 u1 = *(const float4*)&Cs[row * 132 + tx * 8 + 4];
        a8[0] = u0.x + bias; a8[1] = u0.y + bias; a8[2] = u0.z + bias; a8[3] = u0.w + bias;
        a8[4] = u1.x + bias; a8[5] = u1.y + bias; a8[6] = u1.z + bias; a8[7] = u1.w + bias;
        float* op = g_O2 + (size_t)row * COLS + colT;
        *(float4*)op       = make_float4(a8[0], a8[1], a8[2], a8[3]);
        *(float4*)(op + 4) = make_float4(a8[4], a8[5], a8[6], a8[7]);
        float s = 0.f, q = 0.f;
#pragma unroll
        for (int j = 0; j < 8; j++) { s += a8[j]; q += a8[j] * a8[j]; }
#pragma unroll
        for (int off = 8; off; off >>= 1) {
            s += __shfl_xor_sync(0xffffffffu, s, off);
            q += __shfl_xor_sync(0xffffffffu, q, off);
        }
        if ((t & 15) == 0) { atomicAdd(&g_sum1[row], s); atomicAdd(&g_sq1[row], q); }
    }
}

__global__ void finalize1(const float* __restrict__ gamma, const float* __restrict__ beta) {
    const int t = threadIdx.x;
    const float mean = g_sum1[t] * (1.f / COLS);
    const float var = g_sq1[t] * (1.f / COLS) - mean * mean;
    const float a = gamma[t] * rsqrtf(var + 1e-5f);
    g_a1[t] = a;
    g_c1[t] = beta[t] - mean * a;
}

// ---------------- BN2 + ReLU + transpose store ----------------
__global__ void bnout_kernel(float* __restrict__ out) {
    const int idx = blockIdx.x * 256 + threadIdx.x;
    const int e = idx * 4;
    const int row = e >> 16;
    const int col = e & 65535;
    const int b = col >> 12, n = col & 4095;
    float4 v = *(const float4*)&g_O2[(size_t)row * COLS + col];
    const float a = g_a1[row], c = g_c1[row];
    float4 w;
    w.x = fmaxf(0.f, fmaf(a, v.x, c));
    w.y = fmaxf(0.f, fmaf(a, v.y, c));
    w.z = fmaxf(0.f, fmaf(a, v.z, c));
    w.w = fmaxf(0.f, fmaf(a, v.w, c));
    *(float4*)&out[((size_t)(b * 128 + row)) * 4096 + n] = w;
}

extern "C" void kernel_launch(void* const* d_in, const int* in_sizes, int n_in,
                              void* d_out, int out_size) {
    const float* xyz1 = (const float*)d_in[0];
    const float* xyz2 = (const float*)d_in[1];
    const float* p1   = (const float*)d_in[2];
    const float* p2   = (const float*)d_in[3];
    const float* w0   = (const float*)d_in[4];
    const float* b0   = (const float*)d_in[5];
    const float* g0   = (const float*)d_in[6];
    const float* be0  = (const float*)d_in[7];
    const float* w1   = (const float*)d_in[8];
    const float* b1   = (const float*)d_in[9];
    const float* g1   = (const float*)d_in[10];
    const float* be1  = (const float*)d_in[11];
    float* out = (float*)d_out;

    cudaFuncSetAttribute(gemmZ_mma, cudaFuncAttributeMaxDynamicSharedMemorySize, SMEM_BYTES);
    cudaFuncSetAttribute(gemmY_mma, cudaFuncAttributeMaxDynamicSharedMemorySize, SMEM_BYTES);
    cudaFuncSetAttribute(gemmO2_mma, cudaFuncAttributeMaxDynamicSharedMemorySize, SMEM_BYTES);

    prep_kernel<<<1, 256>>>();                                          // 1
    knn_kernel<<<256, 256>>>(xyz1, xyz2);                               // 2
    gemmZ_mma<<<dim3(JCOLS / 128, 6), 512, SMEM_BYTES>>>(w0, p2);       // 3
    gemmY_mma<<<dim3(COLS / 128, 2), 512, SMEM_BYTES>>>(w0, p1, b0);    // 4
    finalize0<<<1, 256>>>(g0, be0);                                     // 5
    gemmO2_mma<<<COLS / 128, 512, SMEM_BYTES>>>(w1, b1);                // 6 (profiled)
    finalize1<<<1, 128>>>(g1, be1);                                     // 7
    bnout_kernel<<<(COLS * 128 / 4) / 256, 256>>>(out);                 // 8
}

// round 11
// speedup vs baseline: 1.2139x; 1.2139x over previous
#include <cuda_runtime.h>
#include <cuda_bf16.h>
#include <cstdint>

#define NB    16
#define NPTS  4096
#define SPTS  1024
#define COLS  65536
#define JCOLS 16384

// fp32 scratch
__device__ __align__(16) float g_Z[3u * 16384u * 256u];   // Z[k][jcol][o 256]
__device__ __align__(16) float g_Yt[65536u * 256u];       // Y transposed: [col][chan 256]
__device__ __align__(16) float g_O2[128u * 65536u];       // [row][col]
// bf16 split weights, transposed [c][o]
__device__ __align__(16) __nv_bfloat16 g_W0Thi[512 * 256], g_W0Tlo[512 * 256];
__device__ __align__(16) __nv_bfloat16 g_W1Thi[256 * 128], g_W1Tlo[256 * 128];
__device__ int   g_idx[65536 * 3];
__device__ float g_w[65536 * 3];
__device__ float g_sum0[256], g_sq0[256], g_a0[256], g_c0[256];
__device__ float g_sum1[128], g_sq1[128], g_a1[128], g_c1[128];

__device__ __forceinline__ void cp16(uint32_t dst, const void* src) {
    asm volatile("cp.async.ca.shared.global [%0], [%1], 16;\n" :: "r"(dst), "l"(src));
}
__device__ __forceinline__ void cp_commit() { asm volatile("cp.async.commit_group;\n"); }
template<int N> __device__ __forceinline__ void cp_wait() {
    asm volatile("cp.async.wait_group %0;\n" :: "n"(N));
}
__device__ __forceinline__ void ldsm4t(uint32_t* r, uint32_t addr) {
    asm volatile("ldmatrix.sync.aligned.m8n8.x4.trans.shared.b16 {%0,%1,%2,%3}, [%4];"
                 : "=r"(r[0]), "=r"(r[1]), "=r"(r[2]), "=r"(r[3]) : "r"(addr));
}
__device__ __forceinline__ void ldsm2t(uint32_t* r, uint32_t addr) {
    asm volatile("ldmatrix.sync.aligned.m8n8.x2.trans.shared.b16 {%0,%1}, [%2];"
                 : "=r"(r[0]), "=r"(r[1]) : "r"(addr));
}
__device__ __forceinline__ void mma16816(float* d, const uint32_t* a, const uint32_t* b) {
    asm volatile("mma.sync.aligned.m16n8k16.row.col.f32.bf16.bf16.f32 "
                 "{%0,%1,%2,%3}, {%4,%5,%6,%7}, {%8,%9}, {%0,%1,%2,%3};"
                 : "+f"(d[0]), "+f"(d[1]), "+f"(d[2]), "+f"(d[3])
                 : "r"(a[0]), "r"(a[1]), "r"(a[2]), "r"(a[3]), "r"(b[0]), "r"(b[1]));
}
__device__ __forceinline__ uint32_t bf2u(__nv_bfloat16 a, __nv_bfloat16 b) {
    return (uint32_t)__bfloat16_as_ushort(a) | ((uint32_t)__bfloat16_as_ushort(b) << 16);
}
__device__ __forceinline__ void split2(float v0, float v1, uint32_t& hi, uint32_t& lo) {
    const __nv_bfloat16 h0 = __float2bfloat16(v0), h1 = __float2bfloat16(v1);
    hi = bf2u(h0, h1);
    lo = bf2u(__float2bfloat16(v0 - __bfloat162float(h0)),
              __float2bfloat16(v1 - __bfloat162float(h1)));
}

// one k16 compute step (R7-proven): 2 m-atoms x 4 n-atoms, 3 split terms
__device__ __forceinline__ void mma_step(uint32_t sbA, uint32_t sbB, const uint32_t* aoff,
                                         const uint32_t* boff, float acc[2][4][4],
                                         uint32_t ksb) {
    uint32_t ahi[2][4], alo[2][4], bhi[4][2], blo[4][2];
#pragma unroll
    for (int am = 0; am < 2; am++) {
        ldsm4t(ahi[am], sbA + aoff[am] + ksb);
        ldsm4t(alo[am], sbA + 8192 + aoff[am] + ksb);
    }
#pragma unroll
    for (int an = 0; an < 4; an++) {
        ldsm2t(bhi[an], sbB + boff[an] + ksb);
        ldsm2t(blo[an], sbB + 8192 + boff[an] + ksb);
    }
#pragma unroll
    for (int am = 0; am < 2; am++)
#pragma unroll
        for (int an = 0; an < 4; an++) {
            mma16816(acc[am][an], ahi[am], bhi[an]);
            mma16816(acc[am][an], ahi[am], blo[an]);
            mma16816(acc[am][an], alo[am], bhi[an]);
        }
}

// Pipelined mainloop (R7 structure). A pre-split bf16 [k][m] global; B fp32 either
// [k][n] n-contig (TR=false) or [n][k] k-contig rows of 32 (TR=true, from g_Yt).
// Converted in-smem (single conv buffer, 2 syncs/k-tile). NT k-tiles of 32.
template<int A_LD, int B_LD, int NT, bool BN, bool TR>
__device__ __forceinline__ void mma_main(char* sm,
        const __nv_bfloat16* aHi, const __nv_bfloat16* aLo,
        const float* bF, const float* bnA, const float* bnC,
        float acc[2][4][4]) {
    constexpr int RAWB  = TR ? 18432 : 16384;
    constexpr int STAGE = 16384 + RAWB;
    constexpr int CONVO = 3 * STAGE;
    const int t = threadIdx.x;
    const int L = t & 31, w = t >> 5;
    const int wm = w >> 2, wn = w & 3;
    const uint32_t sb = (uint32_t)__cvta_generic_to_shared(sm);
    const int lk = t >> 4, lg = t & 15;
    const uint32_t dstA = (uint32_t)(lk * 256 + ((lg ^ (lk & 7)) << 4));

    uint32_t aoff[2], boff[4];
    {
        const int mtx = L >> 3;
        const int kA = (L & 7) + ((mtx & 2) << 2);
        const int mA = wm * 32 + ((mtx & 1) << 3);
#pragma unroll
        for (int am = 0; am < 2; am++)
            aoff[am] = (uint32_t)(kA * 256 + ((((mA + am * 16) >> 3) ^ (kA & 7)) << 4));
        const int kB = L & 15;
#pragma unroll
        for (int an = 0; an < 4; an++) {
            const int nB = wn * 32 + an * 8;
            boff[an] = (uint32_t)(kB * 256 + (((nB >> 3) ^ (kB & 7)) << 4));
        }
    }
#pragma unroll
    for (int am = 0; am < 2; am++)
#pragma unroll
        for (int an = 0; an < 4; an++)
#pragma unroll
            for (int d = 0; d < 4; d++) acc[am][an][d] = 0.f;

    auto load_st = [&](int kt2) {
        const uint32_t buf = sb + (uint32_t)(kt2 % 3) * STAGE;
        const size_t ka = (size_t)kt2 * 32 + lk;
        cp16(buf + dstA, aHi + ka * A_LD + lg * 8);
        cp16(buf + 8192 + dstA, aLo + ka * A_LD + lg * 8);
        if (!TR) {
            const uint32_t dB = 16384u + (uint32_t)(lk * 512 + lg * 32);
            const float* s = bF + ka * B_LD + lg * 8;
            cp16(buf + dB, s);
            cp16(buf + dB + 16, s + 4);
        } else {
#pragma unroll
            for (int h = 0; h < 2; h++) {
                const int c2 = t * 2 + h;
                const int row = c2 >> 3, seg = c2 & 7;
                cp16(buf + 16384u + (uint32_t)(row * 144 + seg * 16),
                     bF + (size_t)row * B_LD + kt2 * 32 + seg * 4);
            }
        }
        cp_commit();
    };

    auto convert = [&](int ckt) {
        char* conv = sm + CONVO;
        if (!TR) {
            const char* bsp = sm + (ckt % 3) * STAGE + 16384 + lk * 512 + lg * 32;
            float4 u0 = *(const float4*)bsp;
            float4 u1 = *(const float4*)(bsp + 16);
            if (BN) {
                const int kabs = ckt * 32 + lk;
                const float a = bnA[kabs], c = bnC[kabs];
                u0.x = fmaxf(0.f, fmaf(a, u0.x, c)); u0.y = fmaxf(0.f, fmaf(a, u0.y, c));
                u0.z = fmaxf(0.f, fmaf(a, u0.z, c)); u0.w = fmaxf(0.f, fmaf(a, u0.w, c));
                u1.x = fmaxf(0.f, fmaf(a, u1.x, c)); u1.y = fmaxf(0.f, fmaf(a, u1.y, c));
                u1.z = fmaxf(0.f, fmaf(a, u1.z, c)); u1.w = fmaxf(0.f, fmaf(a, u1.w, c));
            }
            uint32_t hi[4], lo[4];
            split2(u0.x, u0.y, hi[0], lo[0]);
            split2(u0.z, u0.w, hi[1], lo[1]);
            split2(u1.x, u1.y, hi[2], lo[2]);
            split2(u1.z, u1.w, hi[3], lo[3]);
            char* cd = conv + lk * 256 + ((lg ^ (lk & 7)) << 4);
            *(uint4*)cd = make_uint4(hi[0], hi[1], hi[2], hi[3]);
            *(uint4*)(cd + 8192) = make_uint4(lo[0], lo[1], lo[2], lo[3]);
        } else {
            const int k = t & 31, n0 = (t >> 5) * 8;
            const char* raw = sm + (ckt % 3) * STAGE + 16384;
            float v[8];
#pragma unroll
            for (int i = 0; i < 8; i++)
                v[i] = *(const float*)(raw + (n0 + i) * 144 + k * 4);
            if (BN) {
                const float a = bnA[ckt * 32 + k], c = bnC[ckt * 32 + k];
#pragma unroll
                for (int i = 0; i < 8; i++) v[i] = fmaxf(0.f, fmaf(a, v[i], c));
            }
            uint32_t hi[4], lo[4];
#pragma unroll
            for (int j = 0; j < 4; j++) split2(v[2 * j], v[2 * j + 1], hi[j], lo[j]);
            char* cd = conv + k * 256 + (((n0 >> 3) ^ (k & 7)) << 4);
            *(uint4*)cd = make_uint4(hi[0], hi[1], hi[2], hi[3]);
            *(uint4*)(cd + 8192) = make_uint4(lo[0], lo[1], lo[2], lo[3]);
        }
    };

    load_st(0);
    load_st(1);

#pragma unroll 1
    for (int kt = 0; kt < NT; kt++) {
        cp_wait<1>();
        __syncthreads();
        if (kt + 2 < NT) load_st(kt + 2);
        else cp_commit();
        convert(kt);
        __syncthreads();
        const uint32_t sA = sb + (uint32_t)(kt % 3) * STAGE;
        const uint32_t sB = sb + CONVO;
        mma_step(sA, sB, aoff, boff, acc, 0);
        mma_step(sA, sB, aoff, boff, acc, 4096);
    }
}

// ---------------- prep: zero stats + split weights (transposed [c][o]) ----------------
__global__ void prep_kernel(const float* __restrict__ w0, const float* __restrict__ w1) {
    const int idx = blockIdx.x * 256 + threadIdx.x;   // grid 512 -> 131072
    if (idx < 256) { g_sum0[idx] = 0.f; g_sq0[idx] = 0.f; }
    if (idx < 128) { g_sum1[idx] = 0.f; g_sq1[idx] = 0.f; }
    if (idx < 512 * 256) {
        const float v = w0[(idx & 255) * 512 + (idx >> 8)];
        const __nv_bfloat16 h = __float2bfloat16(v);
        g_W0Thi[idx] = h;
        g_W0Tlo[idx] = __float2bfloat16(v - __bfloat162float(h));
    }
    if (idx < 256 * 128) {
        const float v = w1[(idx & 127) * 256 + (idx >> 7)];
        const __nv_bfloat16 h = __float2bfloat16(v);
        g_W1Thi[idx] = h;
        g_W1Tlo[idx] = __float2bfloat16(v - __bfloat162float(h));
    }
}

// ---------------- 3-NN search + interpolation weights ----------------
__global__ void knn_kernel(const float* __restrict__ xyz1,
                           const float* __restrict__ xyz2) {
    __shared__ float sx[SPTS], sy[SPTS], sz[SPTS], sn[SPTS];
    const int t = threadIdx.x;
    const int b = blockIdx.x >> 4;
    const int qbase = (blockIdx.x & 15) << 8;
    const float* base2 = xyz2 + (size_t)b * 3 * SPTS;
    for (int i = t; i < SPTS; i += 256) {
        float x = base2[i], y = base2[SPTS + i], z = base2[2 * SPTS + i];
        sx[i] = x; sy[i] = y; sz[i] = z; sn[i] = x * x + y * y + z * z;
    }
    __syncthreads();
    const int n = qbase + t;
    const float* base1 = xyz1 + (size_t)b * 3 * NPTS;
    const float qx = base1[n], qy = base1[NPTS + n], qz = base1[2 * NPTS + n];
    const float qn = qx * qx + qy * qy + qz * qz;
    float d0 = 3.4e38f, d1 = 3.4e38f, d2 = 3.4e38f;
    int i0 = 0, i1 = 0, i2 = 0;
#pragma unroll 4
    for (int s = 0; s < SPTS; s++) {
        float d = qn + sn[s] - 2.f * (qx * sx[s] + qy * sy[s] + qz * sz[s]);
        if (d < d2) {
            if (d < d1) {
                if (d < d0) { d2 = d1; i2 = i1; d1 = d0; i1 = i0; d0 = d; i0 = s; }
                else        { d2 = d1; i2 = i1; d1 = d;  i1 = s; }
            } else          { d2 = d;  i2 = s; }
        }
    }
    const float r0 = 1.f / (d0 + 1e-8f);
    const float r1 = 1.f / (d1 + 1e-8f);
    const float r2 = 1.f / (d2 + 1e-8f);
    const float inv = 1.f / (r0 + r1 + r2);
    const int col = b * NPTS + n;
    g_idx[col * 3 + 0] = i0; g_idx[col * 3 + 1] = i1; g_idx[col * 3 + 2] = i2;
    g_w[col * 3 + 0] = r0 * inv; g_w[col * 3 + 1] = r1 * inv; g_w[col * 3 + 2] = r2 * inv;
}

// frag scatter to TRANSPOSED smem C tile: Ct[n 128][132] (conflict-free 4B stores)
#define FRAGS_TO_CT() \
    __syncthreads(); \
    float* Ct = (float*)sm; \
    { \
        const int L = threadIdx.x & 31, w = threadIdx.x >> 5; \
        const int wm = w >> 2, wn = w & 3; \
        _Pragma("unroll") \
        for (int am = 0; am < 2; am++) \
            _Pragma("unroll") \
            for (int an = 0; an < 4; an++) { \
                const int m = wm * 32 + am * 16 + (L >> 2); \
                const int n = wn * 32 + an * 8 + ((L & 3) << 1); \
                Ct[n * 132 + m]             = acc[am][an][0]; \
                Ct[(n + 1) * 132 + m]       = acc[am][an][1]; \
                Ct[n * 132 + m + 8]         = acc[am][an][2]; \
                Ct[(n + 1) * 132 + m + 8]   = acc[am][an][3]; \
            } \
    } \
    __syncthreads();

// frag scatter to normal C tile [m 128][132] (for gemmO2 epilogue)
#define FRAGS_TO_CS() \
    __syncthreads(); \
    float* Cs = (float*)sm; \
    { \
        const int L = threadIdx.x & 31, w = threadIdx.x >> 5; \
        const int wm = w >> 2, wn = w & 3; \
        _Pragma("unroll") \
        for (int am = 0; am < 2; am++) \
            _Pragma("unroll") \
            for (int an = 0; an < 4; an++) { \
                const int m = wm * 32 + am * 16 + (L >> 2); \
                const int n = wn * 32 + an * 8 + ((L & 3) << 1); \
                Cs[m * 132 + n]           = acc[am][an][0]; \
                Cs[m * 132 + n + 1]       = acc[am][an][1]; \
                Cs[(m + 8) * 132 + n]     = acc[am][an][2]; \
                Cs[(m + 8) * 132 + n + 1] = acc[am][an][3]; \
            } \
    } \
    __syncthreads();

#define SMEM_NTR (3 * 32768 + 16384)   // 114688
#define SMEM_TR  (3 * 34816 + 16384)   // 120832

// ---------------- GEMM Z: D[o 128][col 128], K=128; coalesced Z store --------------
__global__ __launch_bounds__(512) void gemmZ_mma(const float* __restrict__ p2) {
    extern __shared__ __align__(16) char sm[];
    const int col0 = blockIdx.x * 128;
    const int kg = blockIdx.y >> 1;
    const int o0 = (blockIdx.y & 1) * 128;
    const int bb = col0 >> 10, sOff = col0 & 1023;

    float acc[2][4][4];
    mma_main<256, 1024, 4, false, false>(sm,
        g_W0Thi + (size_t)(128 + kg * 128) * 256 + o0,
        g_W0Tlo + (size_t)(128 + kg * 128) * 256 + o0,
        p2 + (size_t)bb * 131072 + sOff, nullptr, nullptr, acc);

    FRAGS_TO_CT();

    const int t = threadIdx.x;
    const int L = t & 31, w = t >> 5;
#pragma unroll
    for (int cc = 0; cc < 8; cc++) {
        const int c = w * 8 + cc;
        const int col = col0 + c;
        float4 v = *(const float4*)&Ct[c * 132 + L * 4];
        *(float4*)&g_Z[((size_t)(kg * JCOLS + col)) * 256 + o0 + L * 4] = v;
    }
}

// ---------------- GEMM Y: M=256 (2 y-blocks), K=128; warp-per-col gather ------------
__global__ __launch_bounds__(512) void gemmY_mma(const float* __restrict__ p1,
                                                 const float* __restrict__ bias0) {
    extern __shared__ __align__(16) char sm[];
    const int col0 = blockIdx.x * 128;
    const int m0 = blockIdx.y * 128;
    const int bb = col0 >> 12, nOff = col0 & 4095;

    float acc[2][4][4];
    mma_main<256, 4096, 4, false, false>(sm,
        g_W0Thi + m0, g_W0Tlo + m0,
        p1 + (size_t)bb * 524288 + nOff, nullptr, nullptr, acc);

    FRAGS_TO_CT();

    const int t = threadIdx.x;
    const int L = t & 31, w = t >> 5;
    const float4 bias4 = *(const float4*)&bias0[m0 + L * 4];
    float s4[4] = {0.f, 0.f, 0.f, 0.f}, q4[4] = {0.f, 0.f, 0.f, 0.f};

#pragma unroll
    for (int cc = 0; cc < 8; cc++) {
        const int c = w * 8 + cc;
        const int col = col0 + c;
        float4 v = *(const float4*)&Ct[c * 132 + L * 4];
        const int ia = g_idx[col * 3], ib = g_idx[col * 3 + 1], ic = g_idx[col * 3 + 2];
        const float wa = g_w[col * 3], wb = g_w[col * 3 + 1], wc = g_w[col * 3 + 2];
        const int jb = (col >> 12) << 10;
        float4 z0 = *(const float4*)(g_Z + ((size_t)(jb + ia)) * 256 + m0 + L * 4);
        float4 z1 = *(const float4*)(g_Z + ((size_t)(JCOLS + jb + ib)) * 256 + m0 + L * 4);
        float4 z2 = *(const float4*)(g_Z + ((size_t)(2 * JCOLS + jb + ic)) * 256 + m0 + L * 4);
        v.x += bias4.x + wa * z0.x + wb * z1.x + wc * z2.x;
        v.y += bias4.y + wa * z0.y + wb * z1.y + wc * z2.y;
        v.z += bias4.z + wa * z0.z + wb * z1.z + wc * z2.z;
        v.w += bias4.w + wa * z0.w + wb * z1.w + wc * z2.w;
        *(float4*)&g_Yt[(size_t)col * 256 + m0 + L * 4] = v;
        s4[0] += v.x; s4[1] += v.y; s4[2] += v.z; s4[3] += v.w;
        q4[0] += v.x * v.x; q4[1] += v.y * v.y; q4[2] += v.z * v.z; q4[3] += v.w * v.w;
    }

    // stats: smem reduce across 16 warps, then 2 atomics per row
    __syncthreads();
    float* red = (float*)sm;            // [16][128] sums, [16][128] sq at +2048
#pragma unroll
    for (int r = 0; r < 4; r++) {
        red[w * 128 + L * 4 + r] = s4[r];
        red[2048 + w * 128 + L * 4 + r] = q4[r];
    }
    __syncthreads();
    if (t < 128) {
        float s = 0.f, q = 0.f;
#pragma unroll
        for (int w2 = 0; w2 < 16; w2++) {
            s += red[w2 * 128 + t];
            q += red[2048 + w2 * 128 + t];
        }
        atomicAdd(&g_sum0[m0 + t], s);
        atomicAdd(&g_sq0[m0 + t], q);
    }
}

__global__ void finalize0(const float* __restrict__ gamma, const float* __restrict__ beta) {
    const int t = threadIdx.x;
    const float mean = g_sum0[t] * (1.f / COLS);
    const float var = g_sq0[t] * (1.f / COLS) - mean * mean;
    const float a = gamma[t] * rsqrtf(var + 1e-5f);
    g_a0[t] = a;
    g_c0[t] = beta[t] - mean * a;
}

// ---------------- GEMM O2: M=128, K=256; B from g_Yt (TR), BN0+ReLU fused ------------
__global__ __launch_bounds__(512) void gemmO2_mma(const float* __restrict__ bias1) {
    extern __shared__ __align__(16) char sm[];
    const int col0 = blockIdx.x * 128;

    float acc[2][4][4];
    mma_main<128, 256, 8, true, true>(sm,
        g_W1Thi, g_W1Tlo,
        g_Yt + (size_t)col0 * 256, g_a0, g_c0, acc);

    FRAGS_TO_CS();

    const int t = threadIdx.x;
    const int tx = t & 15, ty = t >> 4;
    const int rowb = ty * 4;
    const int colT = col0 + tx * 8;
#pragma unroll
    for (int i = 0; i < 4; i++) {
        const int row = rowb + i;
        const float bias = bias1[row];
        float a8[8];
        float4 u0 = *(const float4*)&Cs[row * 132 + tx * 8];
        float4 u1 = *(const float4*)&Cs[row * 132 + tx * 8 + 4];
        a8[0] = u0.x + bias; a8[1] = u0.y + bias; a8[2] = u0.z + bias; a8[3] = u0.w + bias;
        a8[4] = u1.x + bias; a8[5] = u1.y + bias; a8[6] = u1.z + bias; a8[7] = u1.w + bias;
        float* op = g_O2 + (size_t)row * COLS + colT;
        *(float4*)op       = make_float4(a8[0], a8[1], a8[2], a8[3]);
        *(float4*)(op + 4) = make_float4(a8[4], a8[5], a8[6], a8[7]);
        float s = 0.f, q = 0.f;
#pragma unroll
        for (int j = 0; j < 8; j++) { s += a8[j]; q += a8[j] * a8[j]; }
#pragma unroll
        for (int off = 8; off; off >>= 1) {
            s += __shfl_xor_sync(0xffffffffu, s, off);
            q += __shfl_xor_sync(0xffffffffu, q, off);
        }
        if ((t & 15) == 0) { atomicAdd(&g_sum1[row], s); atomicAdd(&g_sq1[row], q); }
    }
}

__global__ void finalize1(const float* __restrict__ gamma, const float* __restrict__ beta) {
    const int t = threadIdx.x;
    const float mean = g_sum1[t] * (1.f / COLS);
    const float var = g_sq1[t] * (1.f / COLS) - mean * mean;
    const float a = gamma[t] * rsqrtf(var + 1e-5f);
    g_a1[t] = a;
    g_c1[t] = beta[t] - mean * a;
}

// ---------------- BN2 + ReLU + transpose store ----------------
__global__ void bnout_kernel(float* __restrict__ out) {
    const int idx = blockIdx.x * 256 + threadIdx.x;
    const int e = idx * 4;
    const int row = e >> 16;
    const int col = e & 65535;
    const int b = col >> 12, n = col & 4095;
    float4 v = *(const float4*)&g_O2[(size_t)row * COLS + col];
    const float a = g_a1[row], c = g_c1[row];
    float4 w;
    w.x = fmaxf(0.f, fmaf(a, v.x, c));
    w.y = fmaxf(0.f, fmaf(a, v.y, c));
    w.z = fmaxf(0.f, fmaf(a, v.z, c));
    w.w = fmaxf(0.f, fmaf(a, v.w, c));
    *(float4*)&out[((size_t)(b * 128 + row)) * 4096 + n] = w;
}

extern "C" void kernel_launch(void* const* d_in, const int* in_sizes, int n_in,
                              void* d_out, int out_size) {
    const float* xyz1 = (const float*)d_in[0];
    const float* xyz2 = (const float*)d_in[1];
    const float* p1   = (const float*)d_in[2];
    const float* p2   = (const float*)d_in[3];
    const float* w0   = (const float*)d_in[4];
    const float* b0   = (const float*)d_in[5];
    const float* g0   = (const float*)d_in[6];
    const float* be0  = (const float*)d_in[7];
    const float* w1   = (const float*)d_in[8];
    const float* b1   = (const float*)d_in[9];
    const float* g1   = (const float*)d_in[10];
    const float* be1  = (const float*)d_in[11];
    float* out = (float*)d_out;

    cudaFuncSetAttribute(gemmZ_mma, cudaFuncAttributeMaxDynamicSharedMemorySize, SMEM_NTR);
    cudaFuncSetAttribute(gemmY_mma, cudaFuncAttributeMaxDynamicSharedMemorySize, SMEM_NTR);
    cudaFuncSetAttribute(gemmO2_mma, cudaFuncAttributeMaxDynamicSharedMemorySize, SMEM_TR);

    prep_kernel<<<512, 256>>>(w0, w1);                              // 1
    knn_kernel<<<256, 256>>>(xyz1, xyz2);                           // 2
    gemmZ_mma<<<dim3(JCOLS / 128, 6), 512, SMEM_NTR>>>(p2);         // 3
    gemmY_mma<<<dim3(COLS / 128, 2), 512, SMEM_NTR>>>(p1, b0);      // 4
    finalize0<<<1, 256>>>(g0, be0);                                 // 5
    gemmO2_mma<<<COLS / 128, 512, SMEM_TR>>>(b1);                   // 6 (profiled)
    finalize1<<<1, 128>>>(g1, be1);                                 // 7
    bnout_kernel<<<(COLS * 128 / 4) / 256, 256>>>(out);             // 8
}

// round 13
// speedup vs baseline: 1.2738x; 1.0494x over previous
#include <cuda_runtime.h>
#include <cuda_bf16.h>
#include <cstdint>

#define NB    16
#define NPTS  4096
#define SPTS  1024
#define COLS  65536
#define JCOLS 16384

// fp32 scratch
__device__ __align__(16) float g_Z[3u * 16384u * 256u];   // Z[k][jcol][o 256]
__device__ __align__(16) float g_Yt[65536u * 256u];       // Y transposed: [col][chan 256]
__device__ __align__(16) float g_O2[128u * 65536u];       // [row][col]
// bf16 split weights, transposed [c][o]
__device__ __align__(16) __nv_bfloat16 g_W0Thi[512 * 256], g_W0Tlo[512 * 256];
__device__ __align__(16) __nv_bfloat16 g_W1Thi[256 * 128], g_W1Tlo[256 * 128];
__device__ int   g_idx[65536 * 3];
__device__ float g_w[65536 * 3];
__device__ float g_sum0[256], g_sq0[256], g_a0[256], g_c0[256];
__device__ float g_sum1[128], g_sq1[128], g_a1[128], g_c1[128];

__device__ __forceinline__ void cp16(uint32_t dst, const void* src) {
    asm volatile("cp.async.ca.shared.global [%0], [%1], 16;\n" :: "r"(dst), "l"(src));
}
__device__ __forceinline__ void cp_commit() { asm volatile("cp.async.commit_group;\n"); }
template<int N> __device__ __forceinline__ void cp_wait() {
    asm volatile("cp.async.wait_group %0;\n" :: "n"(N));
}
__device__ __forceinline__ void ldsm4t(uint32_t* r, uint32_t addr) {
    asm volatile("ldmatrix.sync.aligned.m8n8.x4.trans.shared.b16 {%0,%1,%2,%3}, [%4];"
                 : "=r"(r[0]), "=r"(r[1]), "=r"(r[2]), "=r"(r[3]) : "r"(addr));
}
__device__ __forceinline__ void ldsm2t(uint32_t* r, uint32_t addr) {
    asm volatile("ldmatrix.sync.aligned.m8n8.x2.trans.shared.b16 {%0,%1}, [%2];"
                 : "=r"(r[0]), "=r"(r[1]) : "r"(addr));
}
__device__ __forceinline__ void mma16816(float* d, const uint32_t* a, const uint32_t* b) {
    asm volatile("mma.sync.aligned.m16n8k16.row.col.f32.bf16.bf16.f32 "
                 "{%0,%1,%2,%3}, {%4,%5,%6,%7}, {%8,%9}, {%0,%1,%2,%3};"
                 : "+f"(d[0]), "+f"(d[1]), "+f"(d[2]), "+f"(d[3])
                 : "r"(a[0]), "r"(a[1]), "r"(a[2]), "r"(a[3]), "r"(b[0]), "r"(b[1]));
}
__device__ __forceinline__ uint32_t bf2u(__nv_bfloat16 a, __nv_bfloat16 b) {
    return (uint32_t)__bfloat16_as_ushort(a) | ((uint32_t)__bfloat16_as_ushort(b) << 16);
}
__device__ __forceinline__ void split2(float v0, float v1, uint32_t& hi, uint32_t& lo) {
    const __nv_bfloat16 h0 = __float2bfloat16(v0), h1 = __float2bfloat16(v1);
    hi = bf2u(h0, h1);
    lo = bf2u(__float2bfloat16(v0 - __bfloat162float(h0)),
              __float2bfloat16(v1 - __bfloat162float(h1)));
}

// one k16 compute step: 2 m-atoms x 4 n-atoms, 3 split terms
__device__ __forceinline__ void mma_step(uint32_t sbA, uint32_t sbB, const uint32_t* aoff,
                                         const uint32_t* boff, float acc[2][4][4],
                                         uint32_t ksb) {
    uint32_t ahi[2][4], alo[2][4], bhi[4][2], blo[4][2];
#pragma unroll
    for (int am = 0; am < 2; am++) {
        ldsm4t(ahi[am], sbA + aoff[am] + ksb);
        ldsm4t(alo[am], sbA + 8192 + aoff[am] + ksb);
    }
#pragma unroll
    for (int an = 0; an < 4; an++) {
        ldsm2t(bhi[an], sbB + boff[an] + ksb);
        ldsm2t(blo[an], sbB + 8192 + boff[an] + ksb);
    }
#pragma unroll
    for (int am = 0; am < 2; am++)
#pragma unroll
        for (int an = 0; an < 4; an++) {
            mma16816(acc[am][an], ahi[am], bhi[an]);
            mma16816(acc[am][an], ahi[am], blo[an]);
            mma16816(acc[am][an], alo[am], bhi[an]);
        }
}

__device__ __forceinline__ void frag_offsets(int t, uint32_t* aoff, uint32_t* boff) {
    const int L = t & 31, w = t >> 5;
    const int wm = w >> 2, wn = w & 3;
    const int mtx = L >> 3;
    const int kA = (L & 7) + ((mtx & 2) << 2);
    const int mA = wm * 32 + ((mtx & 1) << 3);
#pragma unroll
    for (int am = 0; am < 2; am++)
        aoff[am] = (uint32_t)(kA * 256 + ((((mA + am * 16) >> 3) ^ (kA & 7)) << 4));
    const int kB = L & 15;
#pragma unroll
    for (int an = 0; an < 4; an++) {
        const int nB = wn * 32 + an * 8;
        boff[an] = (uint32_t)(kB * 256 + (((nB >> 3) ^ (kB & 7)) << 4));
    }
}

// ===== NEW register-loader mainloop (non-TR): B via LDG + reg split + direct STS =====
// smem: A stages 0..2 at (kt%3)*16384 (hi +0, lo +8192); conv B at 49152+(kt&1)*16384.
// One __syncthreads per k-tile. Total smem 81920 B.
template<int A_LD, int B_LD, int NT>
__device__ __forceinline__ void mma_mainR(char* sm,
        const __nv_bfloat16* aHi, const __nv_bfloat16* aLo,
        const float* bF, float acc[2][4][4]) {
    const int t = threadIdx.x;
    const uint32_t sb = (uint32_t)__cvta_generic_to_shared(sm);
    const int lk = t >> 4, lg = t & 15;
    const uint32_t dstA = (uint32_t)(lk * 256 + ((lg ^ (lk & 7)) << 4));
    const uint32_t cOff = (uint32_t)(lk * 256 + ((lg ^ (lk & 7)) << 4));

    uint32_t aoff[2], boff[4];
    frag_offsets(t, aoff, boff);
#pragma unroll
    for (int am = 0; am < 2; am++)
#pragma unroll
        for (int an = 0; an < 4; an++)
#pragma unroll
            for (int d = 0; d < 4; d++) acc[am][an][d] = 0.f;

    float4 bv0, bv1;
    auto ldgB = [&](int kt2) {
        const float* s = bF + ((size_t)kt2 * 32 + lk) * B_LD + lg * 8;
        bv0 = *(const float4*)s;
        bv1 = *(const float4*)(s + 4);
    };
    auto stsB = [&](int kt2) {
        uint32_t hi[4], lo[4];
        split2(bv0.x, bv0.y, hi[0], lo[0]);
        split2(bv0.z, bv0.w, hi[1], lo[1]);
        split2(bv1.x, bv1.y, hi[2], lo[2]);
        split2(bv1.z, bv1.w, hi[3], lo[3]);
        char* cd = sm + 49152 + (kt2 & 1) * 16384 + cOff;
        *(uint4*)cd = make_uint4(hi[0], hi[1], hi[2], hi[3]);
        *(uint4*)(cd + 8192) = make_uint4(lo[0], lo[1], lo[2], lo[3]);
    };
    auto loadA = [&](int kt2) {
        const uint32_t buf = sb + (uint32_t)(kt2 % 3) * 16384;
        const size_t ka = (size_t)kt2 * 32 + lk;
        cp16(buf + dstA, aHi + ka * A_LD + lg * 8);
        cp16(buf + 8192 + dstA, aLo + ka * A_LD + lg * 8);
        cp_commit();
    };

    loadA(0);
    loadA(1);
    ldgB(0); stsB(0);
    if (NT > 1) ldgB(1);

#pragma unroll 1
    for (int kt = 0; kt < NT; kt++) {
        cp_wait<1>();
        __syncthreads();              // publishes conv(kt) + A(kt); orders buffer reuse
        if (kt + 1 < NT) stsB(kt + 1);
        if (kt + 2 < NT) { ldgB(kt + 2); loadA(kt + 2); }
        else cp_commit();
        const uint32_t sA = sb + (uint32_t)(kt % 3) * 16384;
        const uint32_t sB = sb + 49152u + (uint32_t)(kt & 1) * 16384;
        mma_step(sA, sB, aoff, boff, acc, 0);
        mma_step(sA, sB, aoff, boff, acc, 4096);
    }
}

// ===== R11 TR mainloop (gemmO2 only): B from g_Yt via cp.async + smem transpose =====
template<int A_LD, int B_LD, int NT, bool BN>
__device__ __forceinline__ void mma_mainTR(char* sm,
        const __nv_bfloat16* aHi, const __nv_bfloat16* aLo,
        const float* bF, const float* bnA, const float* bnC,
        float acc[2][4][4]) {
    constexpr int STAGE = 16384 + 18432;
    constexpr int CONVO = 3 * STAGE;
    const int t = threadIdx.x;
    const uint32_t sb = (uint32_t)__cvta_generic_to_shared(sm);
    const int lk = t >> 4, lg = t & 15;
    const uint32_t dstA = (uint32_t)(lk * 256 + ((lg ^ (lk & 7)) << 4));

    uint32_t aoff[2], boff[4];
    frag_offsets(t, aoff, boff);
#pragma unroll
    for (int am = 0; am < 2; am++)
#pragma unroll
        for (int an = 0; an < 4; an++)
#pragma unroll
            for (int d = 0; d < 4; d++) acc[am][an][d] = 0.f;

    auto load_st = [&](int kt2) {
        const uint32_t buf = sb + (uint32_t)(kt2 % 3) * STAGE;
        const size_t ka = (size_t)kt2 * 32 + lk;
        cp16(buf + dstA, aHi + ka * A_LD + lg * 8);
        cp16(buf + 8192 + dstA, aLo + ka * A_LD + lg * 8);
#pragma unroll
        for (int h = 0; h < 2; h++) {
            const int c2 = t * 2 + h;
            const int row = c2 >> 3, seg = c2 & 7;
            cp16(buf + 16384u + (uint32_t)(row * 144 + seg * 16),
                 bF + (size_t)row * B_LD + kt2 * 32 + seg * 4);
        }
        cp_commit();
    };

    auto convert = [&](int ckt) {
        char* conv = sm + CONVO;
        const int k = t & 31, n0 = (t >> 5) * 8;
        const char* raw = sm + (ckt % 3) * STAGE + 16384;
        float v[8];
#pragma unroll
        for (int i = 0; i < 8; i++)
            v[i] = *(const float*)(raw + (n0 + i) * 144 + k * 4);
        if (BN) {
            const float a = bnA[ckt * 32 + k], c = bnC[ckt * 32 + k];
#pragma unroll
            for (int i = 0; i < 8; i++) v[i] = fmaxf(0.f, fmaf(a, v[i], c));
        }
        uint32_t hi[4], lo[4];
#pragma unroll
        for (int j = 0; j < 4; j++) split2(v[2 * j], v[2 * j + 1], hi[j], lo[j]);
        char* cd = conv + k * 256 + (((n0 >> 3) ^ (k & 7)) << 4);
        *(uint4*)cd = make_uint4(hi[0], hi[1], hi[2], hi[3]);
        *(uint4*)(cd + 8192) = make_uint4(lo[0], lo[1], lo[2], lo[3]);
    };

    load_st(0);
    load_st(1);

#pragma unroll 1
    for (int kt = 0; kt < NT; kt++) {
        cp_wait<1>();
        __syncthreads();
        if (kt + 2 < NT) load_st(kt + 2);
        else cp_commit();
        convert(kt);
        __syncthreads();
        const uint32_t sA = sb + (uint32_t)(kt % 3) * STAGE;
        const uint32_t sB = sb + CONVO;
        mma_step(sA, sB, aoff, boff, acc, 0);
        mma_step(sA, sB, aoff, boff, acc, 4096);
    }
}

// ---------------- prep: zero stats + split weights (transposed [c][o]) ----------------
__global__ void prep_kernel(const float* __restrict__ w0, const float* __restrict__ w1) {
    const int idx = blockIdx.x * 256 + threadIdx.x;
    if (idx < 256) { g_sum0[idx] = 0.f; g_sq0[idx] = 0.f; }
    if (idx < 128) { g_sum1[idx] = 0.f; g_sq1[idx] = 0.f; }
    if (idx < 512 * 256) {
        const float v = w0[(idx & 255) * 512 + (idx >> 8)];
        const __nv_bfloat16 h = __float2bfloat16(v);
        g_W0Thi[idx] = h;
        g_W0Tlo[idx] = __float2bfloat16(v - __bfloat162float(h));
    }
    if (idx < 256 * 128) {
        const float v = w1[(idx & 127) * 256 + (idx >> 7)];
        const __nv_bfloat16 h = __float2bfloat16(v);
        g_W1Thi[idx] = h;
        g_W1Tlo[idx] = __float2bfloat16(v - __bfloat162float(h));
    }
}

// ---------------- 3-NN search + interpolation weights ----------------
__global__ void knn_kernel(const float* __restrict__ xyz1,
                           const float* __restrict__ xyz2) {
    __shared__ float sx[SPTS], sy[SPTS], sz[SPTS], sn[SPTS];
    const int t = threadIdx.x;
    const int b = blockIdx.x >> 4;
    const int qbase = (blockIdx.x & 15) << 8;
    const float* base2 = xyz2 + (size_t)b * 3 * SPTS;
    for (int i = t; i < SPTS; i += 256) {
        float x = base2[i], y = base2[SPTS + i], z = base2[2 * SPTS + i];
        sx[i] = x; sy[i] = y; sz[i] = z; sn[i] = x * x + y * y + z * z;
    }
    __syncthreads();
    const int n = qbase + t;
    const float* base1 = xyz1 + (size_t)b * 3 * NPTS;
    const float qx = base1[n], qy = base1[NPTS + n], qz = base1[2 * NPTS + n];
    const float qn = qx * qx + qy * qy + qz * qz;
    float d0 = 3.4e38f, d1 = 3.4e38f, d2 = 3.4e38f;
    int i0 = 0, i1 = 0, i2 = 0;
#pragma unroll 4
    for (int s = 0; s < SPTS; s++) {
        float d = qn + sn[s] - 2.f * (qx * sx[s] + qy * sy[s] + qz * sz[s]);
        if (d < d2) {
            if (d < d1) {
                if (d < d0) { d2 = d1; i2 = i1; d1 = d0; i1 = i0; d0 = d; i0 = s; }
                else        { d2 = d1; i2 = i1; d1 = d;  i1 = s; }
            } else          { d2 = d;  i2 = s; }
        }
    }
    const float r0 = 1.f / (d0 + 1e-8f);
    const float r1 = 1.f / (d1 + 1e-8f);
    const float r2 = 1.f / (d2 + 1e-8f);
    const float inv = 1.f / (r0 + r1 + r2);
    const int col = b * NPTS + n;
    g_idx[col * 3 + 0] = i0; g_idx[col * 3 + 1] = i1; g_idx[col * 3 + 2] = i2;
    g_w[col * 3 + 0] = r0 * inv; g_w[col * 3 + 1] = r1 * inv; g_w[col * 3 + 2] = r2 * inv;
}

// frag scatter to TRANSPOSED smem C tile: Ct[n 128][132]
#define FRAGS_TO_CT() \
    __syncthreads(); \
    float* Ct = (float*)sm; \
    { \
        const int L = threadIdx.x & 31, w = threadIdx.x >> 5; \
        const int wm = w >> 2, wn = w & 3; \
        _Pragma("unroll") \
        for (int am = 0; am < 2; am++) \
            _Pragma("unroll") \
            for (int an = 0; an < 4; an++) { \
                const int m = wm * 32 + am * 16 + (L >> 2); \
                const int n = wn * 32 + an * 8 + ((L & 3) << 1); \
                Ct[n * 132 + m]             = acc[am][an][0]; \
                Ct[(n + 1) * 132 + m]       = acc[am][an][1]; \
                Ct[n * 132 + m + 8]         = acc[am][an][2]; \
                Ct[(n + 1) * 132 + m + 8]   = acc[am][an][3]; \
            } \
    } \
    __syncthreads();

// frag scatter to normal C tile [m 128][132] (gemmO2 epilogue)
#define FRAGS_TO_CS() \
    __syncthreads(); \
    float* Cs = (float*)sm; \
    { \
        const int L = threadIdx.x & 31, w = threadIdx.x >> 5; \
        const int wm = w >> 2, wn = w & 3; \
        _Pragma("unroll") \
        for (int am = 0; am < 2; am++) \
            _Pragma("unroll") \
            for (int an = 0; an < 4; an++) { \
                const int m = wm * 32 + am * 16 + (L >> 2); \
                const int n = wn * 32 + an * 8 + ((L & 3) << 1); \
                Cs[m * 132 + n]           = acc[am][an][0]; \
                Cs[m * 132 + n + 1]       = acc[am][an][1]; \
                Cs[(m + 8) * 132 + n]     = acc[am][an][2]; \
                Cs[(m + 8) * 132 + n + 1] = acc[am][an][3]; \
            } \
    } \
    __syncthreads();

#define SMEM_R   81920                 // A 3x16K + conv B 2x16K
#define SMEM_TR  (3 * 34816 + 16384)   // 120832

// ---------------- GEMM Z: D[o 128][col 128], K=128; coalesced Z store --------------
__global__ __launch_bounds__(512) void gemmZ_mma(const float* __restrict__ p2) {
    extern __shared__ __align__(16) char sm[];
    const int col0 = blockIdx.x * 128;
    const int kg = blockIdx.y >> 1;
    const int o0 = (blockIdx.y & 1) * 128;
    const int bb = col0 >> 10, sOff = col0 & 1023;

    float acc[2][4][4];
    mma_mainR<256, 1024, 4>(sm,
        g_W0Thi + (size_t)(128 + kg * 128) * 256 + o0,
        g_W0Tlo + (size_t)(128 + kg * 128) * 256 + o0,
        p2 + (size_t)bb * 131072 + sOff, acc);

    FRAGS_TO_CT();

    const int t = threadIdx.x;
    const int L = t & 31, w = t >> 5;
#pragma unroll
    for (int cc = 0; cc < 8; cc++) {
        const int c = w * 8 + cc;
        const int col = col0 + c;
        float4 v = *(const float4*)&Ct[c * 132 + L * 4];
        *(float4*)&g_Z[((size_t)(kg * JCOLS + col)) * 256 + o0 + L * 4] = v;
    }
}

// ---------------- GEMM Y: M=256 (2 y-blocks), K=128; warp-per-col gather ------------
__global__ __launch_bounds__(512) void gemmY_mma(const float* __restrict__ p1,
                                                 const float* __restrict__ bias0) {
    extern __shared__ __align__(16) char sm[];
    const int col0 = blockIdx.x * 128;
    const int m0 = blockIdx.y * 128;
    const int bb = col0 >> 12, nOff = col0 & 4095;

    float acc[2][4][4];
    mma_mainR<256, 4096, 4>(sm,
        g_W0Thi + m0, g_W0Tlo + m0,
        p1 + (size_t)bb * 524288 + nOff, acc);

    FRAGS_TO_CT();

    const int t = threadIdx.x;
    const int L = t & 31, w = t >> 5;
    const float4 bias4 = *(const float4*)&bias0[m0 + L * 4];
    float s4[4] = {0.f, 0.f, 0.f, 0.f}, q4[4] = {0.f, 0.f, 0.f, 0.f};

#pragma unroll
    for (int cc = 0; cc < 8; cc++) {
        const int c = w * 8 + cc;
        const int col = col0 + c;
        float4 v = *(const float4*)&Ct[c * 132 + L * 4];
        const int ia = g_idx[col * 3], ib = g_idx[col * 3 + 1], ic = g_idx[col * 3 + 2];
        const float wa = g_w[col * 3], wb = g_w[col * 3 + 1], wc = g_w[col * 3 + 2];
        const int jb = (col >> 12) << 10;
        float4 z0 = *(const float4*)(g_Z + ((size_t)(jb + ia)) * 256 + m0 + L * 4);
        float4 z1 = *(const float4*)(g_Z + ((size_t)(JCOLS + jb + ib)) * 256 + m0 + L * 4);
        float4 z2 = *(const float4*)(g_Z + ((size_t)(2 * JCOLS + jb + ic)) * 256 + m0 + L * 4);
        v.x += bias4.x + wa * z0.x + wb * z1.x + wc * z2.x;
        v.y += bias4.y + wa * z0.y + wb * z1.y + wc * z2.y;
        v.z += bias4.z + wa * z0.z + wb * z1.z + wc * z2.z;
        v.w += bias4.w + wa * z0.w + wb * z1.w + wc * z2.w;
        *(float4*)&g_Yt[(size_t)col * 256 + m0 + L * 4] = v;
        s4[0] += v.x; s4[1] += v.y; s4[2] += v.z; s4[3] += v.w;
        q4[0] += v.x * v.x; q4[1] += v.y * v.y; q4[2] += v.z * v.z; q4[3] += v.w * v.w;
    }

    __syncthreads();
    float* red = (float*)sm;
#pragma unroll
    for (int r = 0; r < 4; r++) {
        red[w * 128 + L * 4 + r] = s4[r];
        red[2048 + w * 128 + L * 4 + r] = q4[r];
    }
    __syncthreads();
    if (t < 128) {
        float s = 0.f, q = 0.f;
#pragma unroll
        for (int w2 = 0; w2 < 16; w2++) {
            s += red[w2 * 128 + t];
            q += red[2048 + w2 * 128 + t];
        }
        atomicAdd(&g_sum0[m0 + t], s);
        atomicAdd(&g_sq0[m0 + t], q);
    }
}

__global__ void finalize0(const float* __restrict__ gamma, const float* __restrict__ beta) {
    const int t = threadIdx.x;
    const float mean = g_sum0[t] * (1.f / COLS);
    const float var = g_sq0[t] * (1.f / COLS) - mean * mean;
    const float a = gamma[t] * rsqrtf(var + 1e-5f);
    g_a0[t] = a;
    g_c0[t] = beta[t] - mean * a;
}

// ---------------- GEMM O2: M=128, K=256; B from g_Yt (TR), BN0+ReLU fused ------------
__global__ __launch_bounds__(512) void gemmO2_mma(const float* __restrict__ bias1) {
    extern __shared__ __align__(16) char sm[];
    const int col0 = blockIdx.x * 128;

    float acc[2][4][4];
    mma_mainTR<128, 256, 8, true>(sm,
        g_W1Thi, g_W1Tlo,
        g_Yt + (size_t)col0 * 256, g_a0, g_c0, acc);

    FRAGS_TO_CS();

    const int t = threadIdx.x;
    const int tx = t & 15, ty = t >> 4;
    const int rowb = ty * 4;
    const int colT = col0 + tx * 8;
#pragma unroll
    for (int i = 0; i < 4; i++) {
        const int row = rowb + i;
        const float bias = bias1[row];
        float a8[8];
        float4 u0 = *(const float4*)&Cs[row * 132 + tx * 8];
        float4 u1 = *(const float4*)&Cs[row * 132 + tx * 8 + 4];
        a8[0] = u0.x + bias; a8[1] = u0.y + bias; a8[2] = u0.z + bias; a8[3] = u0.w + bias;
        a8[4] = u1.x + bias; a8[5] = u1.y + bias; a8[6] = u1.z + bias; a8[7] = u1.w + bias;
        float* op = g_O2 + (size_t)row * COLS + colT;
        *(float4*)op       = make_float4(a8[0], a8[1], a8[2], a8[3]);
        *(float4*)(op + 4) = make_float4(a8[4], a8[5], a8[6], a8[7]);
        float s = 0.f, q = 0.f;
#pragma unroll
        for (int j = 0; j < 8; j++) { s += a8[j]; q += a8[j] * a8[j]; }
#pragma unroll
        for (int off = 8; off; off >>= 1) {
            s += __shfl_xor_sync(0xffffffffu, s, off);
            q += __shfl_xor_sync(0xffffffffu, q, off);
        }
        if ((t & 15) == 0) { atomicAdd(&g_sum1[row], s); atomicAdd(&g_sq1[row], q); }
    }
}

__global__ void finalize1(const float* __restrict__ gamma, const float* __restrict__ beta) {
    const int t = threadIdx.x;
    const float mean = g_sum1[t] * (1.f / COLS);
    const float var = g_sq1[t] * (1.f / COLS) - mean * mean;
    const float a = gamma[t] * rsqrtf(var + 1e-5f);
    g_a1[t] = a;
    g_c1[t] = beta[t] - mean * a;
}

// ---------------- BN2 + ReLU + transpose store ----------------
__global__ void bnout_kernel(float* __restrict__ out) {
    const int idx = blockIdx.x * 256 + threadIdx.x;
    const int e = idx * 4;
    const int row = e >> 16;
    const int col = e & 65535;
    const int b = col >> 12, n = col & 4095;
    float4 v = *(const float4*)&g_O2[(size_t)row * COLS + col];
    const float a = g_a1[row], c = g_c1[row];
    float4 w;
    w.x = fmaxf(0.f, fmaf(a, v.x, c));
    w.y = fmaxf(0.f, fmaf(a, v.y, c));
    w.z = fmaxf(0.f, fmaf(a, v.z, c));
    w.w = fmaxf(0.f, fmaf(a, v.w, c));
    *(float4*)&out[((size_t)(b * 128 + row)) * 4096 + n] = w;
}

extern "C" void kernel_launch(void* const* d_in, const int* in_sizes, int n_in,
                              void* d_out, int out_size) {
    const float* xyz1 = (const float*)d_in[0];
    const float* xyz2 = (const float*)d_in[1];
    const float* p1   = (const float*)d_in[2];
    const float* p2   = (const float*)d_in[3];
    const float* w0   = (const float*)d_in[4];
    const float* b0   = (const float*)d_in[5];
    const float* g0   = (const float*)d_in[6];
    const float* be0  = (const float*)d_in[7];
    const float* w1   = (const float*)d_in[8];
    const float* b1   = (const float*)d_in[9];
    const float* g1   = (const float*)d_in[10];
    const float* be1  = (const float*)d_in[11];
    float* out = (float*)d_out;

    cudaFuncSetAttribute(gemmZ_mma, cudaFuncAttributeMaxDynamicSharedMemorySize, SMEM_R);
    cudaFuncSetAttribute(gemmY_mma, cudaFuncAttributeMaxDynamicSharedMemorySize, SMEM_R);
    cudaFuncSetAttribute(gemmO2_mma, cudaFuncAttributeMaxDynamicSharedMemorySize, SMEM_TR);

    prep_kernel<<<512, 256>>>(w0, w1);                              // 1
    knn_kernel<<<256, 256>>>(xyz1, xyz2);                           // 2
    gemmZ_mma<<<dim3(JCOLS / 128, 6), 512, SMEM_R>>>(p2);           // 3
    gemmY_mma<<<dim3(COLS / 128, 2), 512, SMEM_R>>>(p1, b0);        // 4
    finalize0<<<1, 256>>>(g0, be0);                                 // 5
    gemmO2_mma<<<COLS / 128, 512, SMEM_TR>>>(b1);                   // 6 (profiled)
    finalize1<<<1, 128>>>(g1, be1);                                 // 7
    bnout_kernel<<<(COLS * 128 / 4) / 256, 256>>>(out);             // 8
}